// round 15
// baseline (speedup 1.0000x reference)
#include <cuda_runtime.h>
#include <cuda_fp16.h>
#include <cstdint>

#define B 4096
#define D 512
#define NT 32              // 4096/128 tiles per dim
#define MARGIN 0.3f
#define LOSS_EPS 1e-12f

// ---------------- device scratch (no runtime allocation allowed) ----------
__device__ float g_sq[B];
__device__ int   g_hp[B];
__device__ int   g_hn[B];
__device__ int   g_ready[NT];          // zero at load; reset by loss_kernel
__device__ __align__(16) __half g_hf[B * D];

// ---------------- PTX helpers (plain sm_80-class PTX only!) ---------------
__device__ __forceinline__ uint32_t smem_u32(const void* p) {
    uint32_t a;
    asm("{ .reg .u64 t; cvta.to.shared.u64 t, %1; cvt.u32.u64 %0, t; }"
        : "=r"(a) : "l"(p));
    return a;
}
__device__ __forceinline__ void cp16(uint32_t dst, const void* src) {
    asm volatile("cp.async.cg.shared.global [%0], [%1], 16;"
                 :: "r"(dst), "l"(src) : "memory");
}
#define CP_COMMIT() asm volatile("cp.async.commit_group;" ::: "memory")
#define CP_WAIT(n)  asm volatile("cp.async.wait_group %0;" :: "n"(n) : "memory")

#define LDSM4(r, addr)                                                        \
    asm volatile("ldmatrix.sync.aligned.m8n8.x4.shared.b16 {%0,%1,%2,%3},[%4];" \
                 : "=r"((r)[0]), "=r"((r)[1]), "=r"((r)[2]), "=r"((r)[3])     \
                 : "r"(addr))

// fp16 inputs, fp32 accumulate
#define MMAF(c, a, b0, b1)                                                    \
    asm volatile("mma.sync.aligned.m16n8k16.row.col.f32.f16.f16.f32 "         \
                 "{%0,%1,%2,%3},{%4,%5,%6,%7},{%8,%9},{%0,%1,%2,%3};"         \
                 : "+f"((c)[0]), "+f"((c)[1]), "+f"((c)[2]), "+f"((c)[3])     \
                 : "r"((a)[0]), "r"((a)[1]), "r"((a)[2]), "r"((a)[3]),        \
                   "r"(b0), "r"(b1))

// ---------------------------------------------------------------------------
// Fused kernel: blocks 0..NT-1 first prep their 128-row block (fp16 round +
// consistent norms + sentinels), publish via g_ready; everyone spin-waits on
// the two row-blocks they need, then runs the R13 GEMM+mining verbatim.
// ---------------------------------------------------------------------------
#define KC 64
#define TILE_BYTES 16384           // 128 rows x 128B
#define STAGE_BYTES (2 * TILE_BYTES)
#define NSTAGE 3
#define NCHUNK (D / KC)            // 8

__global__ __launch_bounds__(256, 2)
void mine_kernel(const float* __restrict__ emb, const int* __restrict__ labels) {
    extern __shared__ char smem[];
    __shared__ int   rLab[128], cLab[128];
    __shared__ float rSq[128], cSq[128];
    __shared__ int   sHpR[128], sHnR[128], sHpC[128], sHnC[128];

    const uint32_t sb = smem_u32(smem);
    const int tid  = threadIdx.x;
    const int wid  = tid >> 5;
    const int lane = tid & 31;

    // map linear bid -> upper-triangle tile (I <= J)
    int I = 0, rem = blockIdx.x;
    while (rem >= NT - I) { rem -= NT - I; I++; }
    const int J = I + rem;
    const bool diag = (I == J);
    const int rowBase = I * 128, colBase = J * 128;

    // ---- inline prep: block b < NT converts row-block b ----
    if (blockIdx.x < NT) {
        const int rb = blockIdx.x;
#pragma unroll 1
        for (int r = 0; r < 16; r++) {
            const int row = rb * 128 + wid * 16 + r;
            const float4* p = reinterpret_cast<const float4*>(emb + (size_t)row * D);
            uint2* h2 = reinterpret_cast<uint2*>(g_hf + (size_t)row * D);
            float4 v[4];
#pragma unroll
            for (int i = 0; i < 4; i++) v[i] = p[lane + 32 * i];
            float s = 0.f;
#pragma unroll
            for (int i = 0; i < 4; i++) {
                float f[4] = {v[i].x, v[i].y, v[i].z, v[i].w};
                unsigned short h[4];
#pragma unroll
                for (int c = 0; c < 4; c++) {
                    __half hb = __float2half(f[c]);
                    float hf = __half2float(hb);
                    s += hf * hf;             // norms consistent w/ rounded data
                    h[c] = __half_as_ushort(hb);
                }
                h2[lane + 32 * i] = make_uint2(
                    (uint32_t)h[0] | ((uint32_t)h[1] << 16),
                    (uint32_t)h[2] | ((uint32_t)h[3] << 16));
            }
#pragma unroll
            for (int o = 16; o; o >>= 1) s += __shfl_xor_sync(0xFFFFFFFFu, s, o);
            if (lane == 0) {
                g_sq[row] = s;
                g_hp[row] = (int)0xFF800000;
                g_hn[row] = 0x7F800000;
            }
        }
        __threadfence();
        __syncthreads();
        if (tid == 0) atomicExch(&g_ready[rb], 1);
    }

    // ---- wait for the two row-blocks this tile needs ----
    if (tid == 0) {
        while (atomicAdd(&g_ready[I], 0) == 0) __nanosleep(128);
        while (atomicAdd(&g_ready[J], 0) == 0) __nanosleep(128);
    }
    __syncthreads();

    if (tid < 128) {
        rLab[tid] = labels[rowBase + tid];
        cLab[tid] = labels[colBase + tid];
        rSq[tid]  = g_sq[rowBase + tid];
        cSq[tid]  = g_sq[colBase + tid];
        sHpR[tid] = (int)0xFF800000; sHnR[tid] = 0x7F800000;
        sHpC[tid] = (int)0xFF800000; sHnC[tid] = 0x7F800000;
    }

    // 2 tiles per stage: A rows, B cols
    const uint4* srcs[2] = {
        reinterpret_cast<const uint4*>(g_hf + (size_t)rowBase * D),
        reinterpret_cast<const uint4*>(g_hf + (size_t)colBase * D) };

    auto load_chunk = [&](int s, int stage) {
        const uint32_t stOff = sb + stage * STAGE_BYTES;
#pragma unroll
        for (int t = 0; t < 2; t++) {
#pragma unroll
            for (int i = 0; i < 4; i++) {
                int idx = tid + 256 * i;
                int row = idx >> 3, seg = idx & 7;
                uint32_t off = (uint32_t)(row * 128 + ((seg * 16) ^ ((row << 4) & 0x70)));
                cp16(stOff + t * TILE_BYTES + off, srcs[t] + row * (D / 8) + s * 8 + seg);
            }
        }
        CP_COMMIT();
    };

    // prologue: 2 stages in flight
    load_chunk(0, 0);
    load_chunk(1, 1);

    // warp layout: warpM = wid&1 (2 x 64 rows), warpN = wid>>1 (4 x 32 cols)
    const int warpM = wid & 1, warpN = wid >> 1;
    const uint32_t rx   = (uint32_t)((lane & 7) << 4);
    const uint32_t cOffA = (uint32_t)((lane >> 4) << 4);
    const uint32_t cOffB = (uint32_t)(((lane >> 3) & 1) << 4);
    uint32_t aOff[4], bOff[2];
#pragma unroll
    for (int mi = 0; mi < 4; mi++)
        aOff[mi] = (uint32_t)((warpM * 64 + mi * 16 + (lane & 15)) * 128);
#pragma unroll
    for (int pr = 0; pr < 2; pr++)
        bOff[pr] = (uint32_t)((warpN * 32 + pr * 16 + (lane & 7) + ((lane >> 4) << 3)) * 128);

    float acc[4][4][4];
#pragma unroll
    for (int mi = 0; mi < 4; mi++)
#pragma unroll
        for (int ni = 0; ni < 4; ni++)
#pragma unroll
            for (int r = 0; r < 4; r++) acc[mi][ni][r] = 0.f;

    __syncthreads();   // covers label/sq/mining-array init too

    for (int s = 0; s < NCHUNK; s++) {
        // chunk s complete? (chunk s+1 may still be in flight)
        if (s + 1 < NCHUNK) { CP_WAIT(1); } else { CP_WAIT(0); }
        __syncthreads();   // ONE sync: all warps finished MMA on stage (s-1)%3
        if (s + 2 < NCHUNK) load_chunk(s + 2, (s + 2) % NSTAGE);  // freed stage

        const uint32_t stOff = sb + (s % NSTAGE) * STAGE_BYTES;
        const uint32_t aB = stOff;
        const uint32_t bB = stOff + TILE_BYTES;

#pragma unroll
        for (int q = 0; q < 4; q++) {
            const uint32_t kb = (uint32_t)(q * 32);
            const uint32_t ca = (kb + cOffA) ^ rx;
            const uint32_t cb = (kb + cOffB) ^ rx;
            uint32_t af[4][4], bf[2][4];

#pragma unroll
            for (int mi = 0; mi < 4; mi++) LDSM4(af[mi], aB + aOff[mi] + ca);
#pragma unroll
            for (int pr = 0; pr < 2; pr++) LDSM4(bf[pr], bB + bOff[pr] + cb);

#pragma unroll
            for (int mi = 0; mi < 4; mi++)
#pragma unroll
                for (int pr = 0; pr < 2; pr++)
#pragma unroll
                    for (int sub = 0; sub < 2; sub++)
                        MMAF(acc[mi][pr * 2 + sub], af[mi],
                             bf[pr][sub * 2], bf[pr][sub * 2 + 1]);
        }
    }

    // ---- mining epilogue ----
    const float NEG_INF = __int_as_float((int)0xFF800000);
    const float POS_INF = __int_as_float(0x7F800000);

    // row-direction: rows of I vs cols of J
#pragma unroll
    for (int mi = 0; mi < 4; mi++) {
#pragma unroll
        for (int h = 0; h < 2; h++) {
            const int rloc = warpM * 64 + mi * 16 + (lane >> 2) + h * 8;
            const int rl = rLab[rloc];
            const float rs = rSq[rloc];
            float hp = NEG_INF, hn = POS_INF;
#pragma unroll
            for (int ni = 0; ni < 4; ni++)
#pragma unroll
                for (int p = 0; p < 2; p++) {
                    const int cloc = warpN * 32 + ni * 8 + (lane & 3) * 2 + p;
                    float d2 = fmaxf(rs + cSq[cloc] - 2.f * acc[mi][ni][h * 2 + p], 0.f);
                    if (rl == cLab[cloc]) {
                        if (!(diag && rloc == cloc)) hp = fmaxf(hp, d2);
                    } else hn = fminf(hn, d2);
                }
            hp = fmaxf(hp, __shfl_xor_sync(0xFFFFFFFFu, hp, 1));
            hp = fmaxf(hp, __shfl_xor_sync(0xFFFFFFFFu, hp, 2));
            hn = fminf(hn, __shfl_xor_sync(0xFFFFFFFFu, hn, 1));
            hn = fminf(hn, __shfl_xor_sync(0xFFFFFFFFu, hn, 2));
            if ((lane & 3) == 0) {
                atomicMax(&sHpR[rloc], __float_as_int(hp));
                atomicMin(&sHnR[rloc], __float_as_int(hn));
            }
        }
    }

    // col-direction (off-diagonal only): rows of J vs cols of I (transpose)
    if (!diag) {
#pragma unroll
        for (int ni = 0; ni < 4; ni++)
#pragma unroll
            for (int p = 0; p < 2; p++) {
                const int cloc = warpN * 32 + ni * 8 + (lane & 3) * 2 + p;
                const int cl = cLab[cloc];
                const float cs = cSq[cloc];
                float hp = NEG_INF, hn = POS_INF;
#pragma unroll
                for (int mi = 0; mi < 4; mi++)
#pragma unroll
                    for (int h = 0; h < 2; h++) {
                        const int rloc = warpM * 64 + mi * 16 + (lane >> 2) + h * 8;
                        float d2 = fmaxf(cs + rSq[rloc] - 2.f * acc[mi][ni][h * 2 + p], 0.f);
                        if (cl == rLab[rloc]) hp = fmaxf(hp, d2);
                        else hn = fminf(hn, d2);
                    }
#pragma unroll
                for (int o = 4; o <= 16; o <<= 1) {
                    hp = fmaxf(hp, __shfl_xor_sync(0xFFFFFFFFu, hp, o));
                    hn = fminf(hn, __shfl_xor_sync(0xFFFFFFFFu, hn, o));
                }
                if ((lane >> 2) == 0) {
                    atomicMax(&sHpC[cloc], __float_as_int(hp));
                    atomicMin(&sHnC[cloc], __float_as_int(hn));
                }
            }
    }

    __syncthreads();
    if (tid < 128) {
        atomicMax(&g_hp[rowBase + tid], sHpR[tid]);
        atomicMin(&g_hn[rowBase + tid], sHnR[tid]);
        if (!diag) {
            atomicMax(&g_hp[colBase + tid], sHpC[tid]);
            atomicMin(&g_hn[colBase + tid], sHnC[tid]);
        }
    }
}

// ---------------------------------------------------------------------------
// Kernel 2: final masked-mean reduce + ready-flag reset for next graph replay.
// ---------------------------------------------------------------------------
__global__ void loss_kernel(float* __restrict__ out) {
    __shared__ float ssum[1024];
    __shared__ float scnt[1024];
    const int tid = threadIdx.x;
    if (tid < NT) g_ready[tid] = 0;           // reset for next replay
    float sum = 0.f, cnt = 0.f;
    for (int r = tid; r < B; r += 1024) {
        int hpb = g_hp[r], hnb = g_hn[r];
        bool valid = (hpb != (int)0xFF800000) && (hnb != 0x7F800000);
        if (valid) {
            float p = sqrtf(fmaxf(__int_as_float(hpb), LOSS_EPS));
            float n = sqrtf(fmaxf(__int_as_float(hnb), LOSS_EPS));
            sum += fmaxf(p - n + MARGIN, 0.f);
            cnt += 1.f;
        }
    }
    ssum[tid] = sum; scnt[tid] = cnt;
    __syncthreads();
    for (int s = 512; s; s >>= 1) {
        if (tid < s) { ssum[tid] += ssum[tid + s]; scnt[tid] += scnt[tid + s]; }
        __syncthreads();
    }
    if (tid == 0)
        out[0] = (scnt[0] > 0.f) ? (ssum[0] / fmaxf(scnt[0], 1.f)) : 0.f;
}

// ---------------------------------------------------------------------------
extern "C" void kernel_launch(void* const* d_in, const int* in_sizes, int n_in,
                              void* d_out, int out_size) {
    const float* emb    = (const float*)d_in[0];
    const int*   labels = (const int*)d_in[1];
    float*       out    = (float*)d_out;

    const int smemBytes = NSTAGE * STAGE_BYTES;   // 96 KB dynamic per CTA
    cudaFuncSetAttribute(mine_kernel, cudaFuncAttributeMaxDynamicSharedMemorySize,
                         smemBytes);

    mine_kernel<<<NT * (NT + 1) / 2, 256, smemBytes>>>(emb, labels);
    loss_kernel<<<1, 1024>>>(out);
}

// round 16
// speedup vs baseline: 1.2137x; 1.2137x over previous
#include <cuda_runtime.h>
#include <cuda_fp16.h>
#include <cstdint>

#define B 4096
#define D 512
#define NT 32              // 4096/128 tiles per dim
#define MARGIN 0.3f
#define LOSS_EPS 1e-12f

// ---------------- device scratch (no runtime allocation allowed) ----------
__device__ float g_sq[B];
__device__ __align__(8) int g_hp[B];
__device__ __align__(8) int g_hn[B];
__device__ __align__(16) __half g_hf[B * D];

// ---------------- PTX helpers (plain sm_80-class PTX only!) ---------------
__device__ __forceinline__ uint32_t smem_u32(const void* p) {
    uint32_t a;
    asm("{ .reg .u64 t; cvta.to.shared.u64 t, %1; cvt.u32.u64 %0, t; }"
        : "=r"(a) : "l"(p));
    return a;
}
__device__ __forceinline__ void cp16(uint32_t dst, const void* src) {
    asm volatile("cp.async.cg.shared.global [%0], [%1], 16;"
                 :: "r"(dst), "l"(src) : "memory");
}
#define CP_COMMIT() asm volatile("cp.async.commit_group;" ::: "memory")
#define CP_WAIT(n)  asm volatile("cp.async.wait_group %0;" :: "n"(n) : "memory")

#define LDSM4(r, addr)                                                        \
    asm volatile("ldmatrix.sync.aligned.m8n8.x4.shared.b16 {%0,%1,%2,%3},[%4];" \
                 : "=r"((r)[0]), "=r"((r)[1]), "=r"((r)[2]), "=r"((r)[3])     \
                 : "r"(addr))

// fp16 inputs, fp32 accumulate
#define MMAF(c, a, b0, b1)                                                    \
    asm volatile("mma.sync.aligned.m16n8k16.row.col.f32.f16.f16.f32 "         \
                 "{%0,%1,%2,%3},{%4,%5,%6,%7},{%8,%9},{%0,%1,%2,%3};"         \
                 : "+f"((c)[0]), "+f"((c)[1]), "+f"((c)[2]), "+f"((c)[3])     \
                 : "r"((a)[0]), "r"((a)[1]), "r"((a)[2]), "r"((a)[3]),        \
                   "r"(b0), "r"(b1))

// ---------------------------------------------------------------------------
// Kernel 1: fp16 round + sq norms OF THE ROUNDED VALUES + sentinel init.
//   Two warps per row (R14 form).
// ---------------------------------------------------------------------------
__global__ void prep_kernel(const float* __restrict__ emb) {
    __shared__ float part[8];
    const int tid  = threadIdx.x;
    const int warp = tid >> 5;          // 0..7
    const int lane = tid & 31;
    const int half = warp & 1;          // which 256-elem half of the row
    const int row  = blockIdx.x * 4 + (warp >> 1);

    const float4* p = reinterpret_cast<const float4*>(emb + (size_t)row * D) + half * 64;
    uint2* h2 = reinterpret_cast<uint2*>(g_hf + (size_t)row * D) + half * 64;

    float s = 0.f;
#pragma unroll
    for (int i = 0; i < 2; i++) {
        float4 v = p[lane + 32 * i];
        float f[4] = {v.x, v.y, v.z, v.w};
        unsigned short h[4];
#pragma unroll
        for (int c = 0; c < 4; c++) {
            __half hb = __float2half(f[c]);
            float hf = __half2float(hb);
            s += hf * hf;                     // norms consistent w/ rounded data
            h[c] = __half_as_ushort(hb);
        }
        h2[lane + 32 * i] = make_uint2((uint32_t)h[0] | ((uint32_t)h[1] << 16),
                                       (uint32_t)h[2] | ((uint32_t)h[3] << 16));
    }
#pragma unroll
    for (int o = 16; o; o >>= 1) s += __shfl_xor_sync(0xFFFFFFFFu, s, o);
    if (lane == 0) part[warp] = s;
    __syncthreads();
    if (tid < 4) {
        int r = blockIdx.x * 4 + tid;
        g_sq[r] = part[2 * tid] + part[2 * tid + 1];
        g_hp[r] = (int)0xFF800000;
        g_hn[r] = 0x7F800000;
    }
}

// ---------------------------------------------------------------------------
// Kernel 2: single-pass fp16 HMMA GEMM, upper-triangle tiles + dual mining
//   tile 128x128, KC=64, 3-stage cp.async / ONE sync per chunk, 2 CTAs/SM
//   (R13/R14 structure, verbatim — best measured 41.6us config)
// ---------------------------------------------------------------------------
#define KC 64
#define TILE_BYTES 16384           // 128 rows x 128B
#define STAGE_BYTES (2 * TILE_BYTES)
#define NSTAGE 3
#define NCHUNK (D / KC)            // 8

__global__ __launch_bounds__(256, 2)
void mine_kernel(const int* __restrict__ labels) {
    extern __shared__ char smem[];
    __shared__ int   rLab[128], cLab[128];
    __shared__ float rSq[128], cSq[128];
    __shared__ int   sHpR[128], sHnR[128], sHpC[128], sHnC[128];

    const uint32_t sb = smem_u32(smem);
    const int tid  = threadIdx.x;
    const int wid  = tid >> 5;
    const int lane = tid & 31;

    // map linear bid -> upper-triangle tile (I <= J)
    int I = 0, rem = blockIdx.x;
    while (rem >= NT - I) { rem -= NT - I; I++; }
    const int J = I + rem;
    const bool diag = (I == J);
    const int rowBase = I * 128, colBase = J * 128;

    if (tid < 128) {
        rLab[tid] = labels[rowBase + tid];
        cLab[tid] = labels[colBase + tid];
        rSq[tid]  = g_sq[rowBase + tid];
        cSq[tid]  = g_sq[colBase + tid];
        sHpR[tid] = (int)0xFF800000; sHnR[tid] = 0x7F800000;
        sHpC[tid] = (int)0xFF800000; sHnC[tid] = 0x7F800000;
    }

    // 2 tiles per stage: A rows, B cols
    const uint4* srcs[2] = {
        reinterpret_cast<const uint4*>(g_hf + (size_t)rowBase * D),
        reinterpret_cast<const uint4*>(g_hf + (size_t)colBase * D) };

    auto load_chunk = [&](int s, int stage) {
        const uint32_t stOff = sb + stage * STAGE_BYTES;
#pragma unroll
        for (int t = 0; t < 2; t++) {
#pragma unroll
            for (int i = 0; i < 4; i++) {
                int idx = tid + 256 * i;
                int row = idx >> 3, seg = idx & 7;
                uint32_t off = (uint32_t)(row * 128 + ((seg * 16) ^ ((row << 4) & 0x70)));
                cp16(stOff + t * TILE_BYTES + off, srcs[t] + row * (D / 8) + s * 8 + seg);
            }
        }
        CP_COMMIT();
    };

    // prologue: 2 stages in flight
    load_chunk(0, 0);
    load_chunk(1, 1);

    // warp layout: warpM = wid&1 (2 x 64 rows), warpN = wid>>1 (4 x 32 cols)
    const int warpM = wid & 1, warpN = wid >> 1;
    const uint32_t rx   = (uint32_t)((lane & 7) << 4);
    const uint32_t cOffA = (uint32_t)((lane >> 4) << 4);
    const uint32_t cOffB = (uint32_t)(((lane >> 3) & 1) << 4);
    uint32_t aOff[4], bOff[2];
#pragma unroll
    for (int mi = 0; mi < 4; mi++)
        aOff[mi] = (uint32_t)((warpM * 64 + mi * 16 + (lane & 15)) * 128);
#pragma unroll
    for (int pr = 0; pr < 2; pr++)
        bOff[pr] = (uint32_t)((warpN * 32 + pr * 16 + (lane & 7) + ((lane >> 4) << 3)) * 128);

    float acc[4][4][4];
#pragma unroll
    for (int mi = 0; mi < 4; mi++)
#pragma unroll
        for (int ni = 0; ni < 4; ni++)
#pragma unroll
            for (int r = 0; r < 4; r++) acc[mi][ni][r] = 0.f;

    __syncthreads();   // covers label/sq/mining-array init too

    for (int s = 0; s < NCHUNK; s++) {
        // chunk s complete? (chunk s+1 may still be in flight)
        if (s + 1 < NCHUNK) { CP_WAIT(1); } else { CP_WAIT(0); }
        __syncthreads();   // ONE sync: all warps finished MMA on stage (s-1)%3
        if (s + 2 < NCHUNK) load_chunk(s + 2, (s + 2) % NSTAGE);  // freed stage

        const uint32_t stOff = sb + (s % NSTAGE) * STAGE_BYTES;
        const uint32_t aB = stOff;
        const uint32_t bB = stOff + TILE_BYTES;

#pragma unroll
        for (int q = 0; q < 4; q++) {
            const uint32_t kb = (uint32_t)(q * 32);
            const uint32_t ca = (kb + cOffA) ^ rx;
            const uint32_t cb = (kb + cOffB) ^ rx;
            uint32_t af[4][4], bf[2][4];

#pragma unroll
            for (int mi = 0; mi < 4; mi++) LDSM4(af[mi], aB + aOff[mi] + ca);
#pragma unroll
            for (int pr = 0; pr < 2; pr++) LDSM4(bf[pr], bB + bOff[pr] + cb);

#pragma unroll
            for (int mi = 0; mi < 4; mi++)
#pragma unroll
                for (int pr = 0; pr < 2; pr++)
#pragma unroll
                    for (int sub = 0; sub < 2; sub++)
                        MMAF(acc[mi][pr * 2 + sub], af[mi],
                             bf[pr][sub * 2], bf[pr][sub * 2 + 1]);
        }
    }

    // ---- mining epilogue ----
    const float NEG_INF = __int_as_float((int)0xFF800000);
    const float POS_INF = __int_as_float(0x7F800000);

    // row-direction: rows of I vs cols of J
#pragma unroll
    for (int mi = 0; mi < 4; mi++) {
#pragma unroll
        for (int h = 0; h < 2; h++) {
            const int rloc = warpM * 64 + mi * 16 + (lane >> 2) + h * 8;
            const int rl = rLab[rloc];
            const float rs = rSq[rloc];
            float hp = NEG_INF, hn = POS_INF;
#pragma unroll
            for (int ni = 0; ni < 4; ni++)
#pragma unroll
                for (int p = 0; p < 2; p++) {
                    const int cloc = warpN * 32 + ni * 8 + (lane & 3) * 2 + p;
                    float d2 = fmaxf(rs + cSq[cloc] - 2.f * acc[mi][ni][h * 2 + p], 0.f);
                    if (rl == cLab[cloc]) {
                        if (!(diag && rloc == cloc)) hp = fmaxf(hp, d2);
                    } else hn = fminf(hn, d2);
                }
            hp = fmaxf(hp, __shfl_xor_sync(0xFFFFFFFFu, hp, 1));
            hp = fmaxf(hp, __shfl_xor_sync(0xFFFFFFFFu, hp, 2));
            hn = fminf(hn, __shfl_xor_sync(0xFFFFFFFFu, hn, 1));
            hn = fminf(hn, __shfl_xor_sync(0xFFFFFFFFu, hn, 2));
            if ((lane & 3) == 0) {
                atomicMax(&sHpR[rloc], __float_as_int(hp));
                atomicMin(&sHnR[rloc], __float_as_int(hn));
            }
        }
    }

    // col-direction (off-diagonal only): rows of J vs cols of I (transpose)
    if (!diag) {
#pragma unroll
        for (int ni = 0; ni < 4; ni++)
#pragma unroll
            for (int p = 0; p < 2; p++) {
                const int cloc = warpN * 32 + ni * 8 + (lane & 3) * 2 + p;
                const int cl = cLab[cloc];
                const float cs = cSq[cloc];
                float hp = NEG_INF, hn = POS_INF;
#pragma unroll
                for (int mi = 0; mi < 4; mi++)
#pragma unroll
                    for (int h = 0; h < 2; h++) {
                        const int rloc = warpM * 64 + mi * 16 + (lane >> 2) + h * 8;
                        float d2 = fmaxf(cs + rSq[rloc] - 2.f * acc[mi][ni][h * 2 + p], 0.f);
                        if (cl == rLab[rloc]) hp = fmaxf(hp, d2);
                        else hn = fminf(hn, d2);
                    }
#pragma unroll
                for (int o = 4; o <= 16; o <<= 1) {
                    hp = fmaxf(hp, __shfl_xor_sync(0xFFFFFFFFu, hp, o));
                    hn = fminf(hn, __shfl_xor_sync(0xFFFFFFFFu, hn, o));
                }
                if ((lane >> 2) == 0) {
                    atomicMax(&sHpC[cloc], __float_as_int(hp));
                    atomicMin(&sHnC[cloc], __float_as_int(hn));
                }
            }
    }

    __syncthreads();
    if (tid < 128) {
        atomicMax(&g_hp[rowBase + tid], sHpR[tid]);
        atomicMin(&g_hn[rowBase + tid], sHnR[tid]);
        if (!diag) {
            atomicMax(&g_hp[colBase + tid], sHpC[tid]);
            atomicMin(&g_hn[colBase + tid], sHnC[tid]);
        }
    }
}

// ---------------------------------------------------------------------------
// Kernel 3: final masked-mean reduce. 1024 threads, vectorized int2 reads
//   (2 independent 8B loads per thread instead of 4 scalar loads).
// ---------------------------------------------------------------------------
__global__ void loss_kernel(float* __restrict__ out) {
    __shared__ float ssum[1024];
    __shared__ float scnt[1024];
    const int tid = threadIdx.x;
    const int2* hp2 = reinterpret_cast<const int2*>(g_hp);
    const int2* hn2 = reinterpret_cast<const int2*>(g_hn);

    // each thread owns pair index tid and tid+1024 -> rows [2t,2t+1], [2t+2048..]
    int2 hpa = hp2[tid],        hna = hn2[tid];
    int2 hpb = hp2[tid + 1024], hnb2 = hn2[tid + 1024];

    float sum = 0.f, cnt = 0.f;
    int hps[4] = {hpa.x, hpa.y, hpb.x, hpb.y};
    int hns[4] = {hna.x, hna.y, hnb2.x, hnb2.y};
#pragma unroll
    for (int k = 0; k < 4; k++) {
        bool valid = (hps[k] != (int)0xFF800000) && (hns[k] != 0x7F800000);
        if (valid) {
            float p = sqrtf(fmaxf(__int_as_float(hps[k]), LOSS_EPS));
            float n = sqrtf(fmaxf(__int_as_float(hns[k]), LOSS_EPS));
            sum += fmaxf(p - n + MARGIN, 0.f);
            cnt += 1.f;
        }
    }
    ssum[tid] = sum; scnt[tid] = cnt;
    __syncthreads();
    for (int s = 512; s; s >>= 1) {
        if (tid < s) { ssum[tid] += ssum[tid + s]; scnt[tid] += scnt[tid + s]; }
        __syncthreads();
    }
    if (tid == 0)
        out[0] = (scnt[0] > 0.f) ? (ssum[0] / fmaxf(scnt[0], 1.f)) : 0.f;
}

// ---------------------------------------------------------------------------
extern "C" void kernel_launch(void* const* d_in, const int* in_sizes, int n_in,
                              void* d_out, int out_size) {
    const float* emb    = (const float*)d_in[0];
    const int*   labels = (const int*)d_in[1];
    float*       out    = (float*)d_out;

    const int smemBytes = NSTAGE * STAGE_BYTES;   // 96 KB dynamic per CTA
    cudaFuncSetAttribute(mine_kernel, cudaFuncAttributeMaxDynamicSharedMemorySize,
                         smemBytes);

    prep_kernel<<<B / 4, 256>>>(emb);
    mine_kernel<<<NT * (NT + 1) / 2, 256, smemBytes>>>(labels);
    loss_kernel<<<1, 1024>>>(out);
}

// round 17
// speedup vs baseline: 1.2226x; 1.0073x over previous
#include <cuda_runtime.h>
#include <cuda_fp16.h>
#include <cstdint>

#define B 4096
#define D 512
#define NT 32              // 4096/128 tiles per dim
#define MARGIN 0.3f
#define LOSS_EPS 1e-12f

// ---------------- device scratch (no runtime allocation allowed) ----------
__device__ float g_sq[B];
__device__ __align__(8) int g_hp[B];
__device__ __align__(8) int g_hn[B];
__device__ __align__(16) __half g_hf[B * D];

// ---------------- PTX helpers (plain sm_80-class PTX only!) ---------------
__device__ __forceinline__ uint32_t smem_u32(const void* p) {
    uint32_t a;
    asm("{ .reg .u64 t; cvta.to.shared.u64 t, %1; cvt.u32.u64 %0, t; }"
        : "=r"(a) : "l"(p));
    return a;
}
__device__ __forceinline__ void cp16(uint32_t dst, const void* src) {
    asm volatile("cp.async.cg.shared.global [%0], [%1], 16;"
                 :: "r"(dst), "l"(src) : "memory");
}
#define CP_COMMIT() asm volatile("cp.async.commit_group;" ::: "memory")
#define CP_WAIT(n)  asm volatile("cp.async.wait_group %0;" :: "n"(n) : "memory")

#define LDSM4(r, addr)                                                        \
    asm volatile("ldmatrix.sync.aligned.m8n8.x4.shared.b16 {%0,%1,%2,%3},[%4];" \
                 : "=r"((r)[0]), "=r"((r)[1]), "=r"((r)[2]), "=r"((r)[3])     \
                 : "r"(addr))

// fp16 inputs, fp32 accumulate
#define MMAF(c, a, b0, b1)                                                    \
    asm volatile("mma.sync.aligned.m16n8k16.row.col.f32.f16.f16.f32 "         \
                 "{%0,%1,%2,%3},{%4,%5,%6,%7},{%8,%9},{%0,%1,%2,%3};"         \
                 : "+f"((c)[0]), "+f"((c)[1]), "+f"((c)[2]), "+f"((c)[3])     \
                 : "r"((a)[0]), "r"((a)[1]), "r"((a)[2]), "r"((a)[3]),        \
                   "r"(b0), "r"(b1))

// ---------------------------------------------------------------------------
// Kernel 1: fp16 round + sq norms OF THE ROUNDED VALUES + sentinel init.
//   Two warps per row; each thread owns 8 contiguous elements:
//   2 back-to-back float4 loads -> 1 coalesced uint4 store.
// ---------------------------------------------------------------------------
__global__ void prep_kernel(const float* __restrict__ emb) {
    __shared__ float part[8];
    const int tid  = threadIdx.x;
    const int warp = tid >> 5;          // 0..7
    const int lane = tid & 31;
    const int half = warp & 1;          // which 256-elem half of the row
    const int row  = blockIdx.x * 4 + (warp >> 1);

    const float4* pf = reinterpret_cast<const float4*>(emb + (size_t)row * D)
                       + half * 64 + lane * 2;
    uint4* h4 = reinterpret_cast<uint4*>(g_hf + (size_t)row * D) + half * 32 + lane;

    float4 v0 = pf[0];
    float4 v1 = pf[1];

    float f[8] = {v0.x, v0.y, v0.z, v0.w, v1.x, v1.y, v1.z, v1.w};
    unsigned short h[8];
    float s = 0.f;
#pragma unroll
    for (int c = 0; c < 8; c++) {
        __half hb = __float2half(f[c]);
        float hf = __half2float(hb);
        s += hf * hf;                         // norms consistent w/ rounded data
        h[c] = __half_as_ushort(hb);
    }
    h4[0] = make_uint4((uint32_t)h[0] | ((uint32_t)h[1] << 16),
                       (uint32_t)h[2] | ((uint32_t)h[3] << 16),
                       (uint32_t)h[4] | ((uint32_t)h[5] << 16),
                       (uint32_t)h[6] | ((uint32_t)h[7] << 16));

#pragma unroll
    for (int o = 16; o; o >>= 1) s += __shfl_xor_sync(0xFFFFFFFFu, s, o);
    if (lane == 0) part[warp] = s;
    __syncthreads();
    if (tid < 4) {
        int r = blockIdx.x * 4 + tid;
        g_sq[r] = part[2 * tid] + part[2 * tid + 1];
        g_hp[r] = (int)0xFF800000;
        g_hn[r] = 0x7F800000;
    }
}

// ---------------------------------------------------------------------------
// Kernel 2: single-pass fp16 HMMA GEMM, upper-triangle tiles + dual mining
//   tile 128x128, KC=64, 3-stage cp.async / ONE sync per chunk, 2 CTAs/SM
//   (R13/R16 structure, verbatim — best measured config)
// ---------------------------------------------------------------------------
#define KC 64
#define TILE_BYTES 16384           // 128 rows x 128B
#define STAGE_BYTES (2 * TILE_BYTES)
#define NSTAGE 3
#define NCHUNK (D / KC)            // 8

__global__ __launch_bounds__(256, 2)
void mine_kernel(const int* __restrict__ labels) {
    extern __shared__ char smem[];
    __shared__ int   rLab[128], cLab[128];
    __shared__ float rSq[128], cSq[128];
    __shared__ int   sHpR[128], sHnR[128], sHpC[128], sHnC[128];

    const uint32_t sb = smem_u32(smem);
    const int tid  = threadIdx.x;
    const int wid  = tid >> 5;
    const int lane = tid & 31;

    // map linear bid -> upper-triangle tile (I <= J)
    int I = 0, rem = blockIdx.x;
    while (rem >= NT - I) { rem -= NT - I; I++; }
    const int J = I + rem;
    const bool diag = (I == J);
    const int rowBase = I * 128, colBase = J * 128;

    if (tid < 128) {
        rLab[tid] = labels[rowBase + tid];
        cLab[tid] = labels[colBase + tid];
        rSq[tid]  = g_sq[rowBase + tid];
        cSq[tid]  = g_sq[colBase + tid];
        sHpR[tid] = (int)0xFF800000; sHnR[tid] = 0x7F800000;
        sHpC[tid] = (int)0xFF800000; sHnC[tid] = 0x7F800000;
    }

    // 2 tiles per stage: A rows, B cols
    const uint4* srcs[2] = {
        reinterpret_cast<const uint4*>(g_hf + (size_t)rowBase * D),
        reinterpret_cast<const uint4*>(g_hf + (size_t)colBase * D) };

    auto load_chunk = [&](int s, int stage) {
        const uint32_t stOff = sb + stage * STAGE_BYTES;
#pragma unroll
        for (int t = 0; t < 2; t++) {
#pragma unroll
            for (int i = 0; i < 4; i++) {
                int idx = tid + 256 * i;
                int row = idx >> 3, seg = idx & 7;
                uint32_t off = (uint32_t)(row * 128 + ((seg * 16) ^ ((row << 4) & 0x70)));
                cp16(stOff + t * TILE_BYTES + off, srcs[t] + row * (D / 8) + s * 8 + seg);
            }
        }
        CP_COMMIT();
    };

    // prologue: 2 stages in flight
    load_chunk(0, 0);
    load_chunk(1, 1);

    // warp layout: warpM = wid&1 (2 x 64 rows), warpN = wid>>1 (4 x 32 cols)
    const int warpM = wid & 1, warpN = wid >> 1;
    const uint32_t rx   = (uint32_t)((lane & 7) << 4);
    const uint32_t cOffA = (uint32_t)((lane >> 4) << 4);
    const uint32_t cOffB = (uint32_t)(((lane >> 3) & 1) << 4);
    uint32_t aOff[4], bOff[2];
#pragma unroll
    for (int mi = 0; mi < 4; mi++)
        aOff[mi] = (uint32_t)((warpM * 64 + mi * 16 + (lane & 15)) * 128);
#pragma unroll
    for (int pr = 0; pr < 2; pr++)
        bOff[pr] = (uint32_t)((warpN * 32 + pr * 16 + (lane & 7) + ((lane >> 4) << 3)) * 128);

    float acc[4][4][4];
#pragma unroll
    for (int mi = 0; mi < 4; mi++)
#pragma unroll
        for (int ni = 0; ni < 4; ni++)
#pragma unroll
            for (int r = 0; r < 4; r++) acc[mi][ni][r] = 0.f;

    __syncthreads();   // covers label/sq/mining-array init too

    for (int s = 0; s < NCHUNK; s++) {
        // chunk s complete? (chunk s+1 may still be in flight)
        if (s + 1 < NCHUNK) { CP_WAIT(1); } else { CP_WAIT(0); }
        __syncthreads();   // ONE sync: all warps finished MMA on stage (s-1)%3
        if (s + 2 < NCHUNK) load_chunk(s + 2, (s + 2) % NSTAGE);  // freed stage

        const uint32_t stOff = sb + (s % NSTAGE) * STAGE_BYTES;
        const uint32_t aB = stOff;
        const uint32_t bB = stOff + TILE_BYTES;

#pragma unroll
        for (int q = 0; q < 4; q++) {
            const uint32_t kb = (uint32_t)(q * 32);
            const uint32_t ca = (kb + cOffA) ^ rx;
            const uint32_t cb = (kb + cOffB) ^ rx;
            uint32_t af[4][4], bf[2][4];

#pragma unroll
            for (int mi = 0; mi < 4; mi++) LDSM4(af[mi], aB + aOff[mi] + ca);
#pragma unroll
            for (int pr = 0; pr < 2; pr++) LDSM4(bf[pr], bB + bOff[pr] + cb);

#pragma unroll
            for (int mi = 0; mi < 4; mi++)
#pragma unroll
                for (int pr = 0; pr < 2; pr++)
#pragma unroll
                    for (int sub = 0; sub < 2; sub++)
                        MMAF(acc[mi][pr * 2 + sub], af[mi],
                             bf[pr][sub * 2], bf[pr][sub * 2 + 1]);
        }
    }

    // ---- mining epilogue ----
    const float NEG_INF = __int_as_float((int)0xFF800000);
    const float POS_INF = __int_as_float(0x7F800000);

    // row-direction: rows of I vs cols of J
#pragma unroll
    for (int mi = 0; mi < 4; mi++) {
#pragma unroll
        for (int h = 0; h < 2; h++) {
            const int rloc = warpM * 64 + mi * 16 + (lane >> 2) + h * 8;
            const int rl = rLab[rloc];
            const float rs = rSq[rloc];
            float hp = NEG_INF, hn = POS_INF;
#pragma unroll
            for (int ni = 0; ni < 4; ni++)
#pragma unroll
                for (int p = 0; p < 2; p++) {
                    const int cloc = warpN * 32 + ni * 8 + (lane & 3) * 2 + p;
                    float d2 = fmaxf(rs + cSq[cloc] - 2.f * acc[mi][ni][h * 2 + p], 0.f);
                    if (rl == cLab[cloc]) {
                        if (!(diag && rloc == cloc)) hp = fmaxf(hp, d2);
                    } else hn = fminf(hn, d2);
                }
            hp = fmaxf(hp, __shfl_xor_sync(0xFFFFFFFFu, hp, 1));
            hp = fmaxf(hp, __shfl_xor_sync(0xFFFFFFFFu, hp, 2));
            hn = fminf(hn, __shfl_xor_sync(0xFFFFFFFFu, hn, 1));
            hn = fminf(hn, __shfl_xor_sync(0xFFFFFFFFu, hn, 2));
            if ((lane & 3) == 0) {
                atomicMax(&sHpR[rloc], __float_as_int(hp));
                atomicMin(&sHnR[rloc], __float_as_int(hn));
            }
        }
    }

    // col-direction (off-diagonal only): rows of J vs cols of I (transpose)
    if (!diag) {
#pragma unroll
        for (int ni = 0; ni < 4; ni++)
#pragma unroll
            for (int p = 0; p < 2; p++) {
                const int cloc = warpN * 32 + ni * 8 + (lane & 3) * 2 + p;
                const int cl = cLab[cloc];
                const float cs = cSq[cloc];
                float hp = NEG_INF, hn = POS_INF;
#pragma unroll
                for (int mi = 0; mi < 4; mi++)
#pragma unroll
                    for (int h = 0; h < 2; h++) {
                        const int rloc = warpM * 64 + mi * 16 + (lane >> 2) + h * 8;
                        float d2 = fmaxf(cs + rSq[rloc] - 2.f * acc[mi][ni][h * 2 + p], 0.f);
                        if (cl == rLab[rloc]) hp = fmaxf(hp, d2);
                        else hn = fminf(hn, d2);
                    }
#pragma unroll
                for (int o = 4; o <= 16; o <<= 1) {
                    hp = fmaxf(hp, __shfl_xor_sync(0xFFFFFFFFu, hp, o));
                    hn = fminf(hn, __shfl_xor_sync(0xFFFFFFFFu, hn, o));
                }
                if ((lane >> 2) == 0) {
                    atomicMax(&sHpC[cloc], __float_as_int(hp));
                    atomicMin(&sHnC[cloc], __float_as_int(hn));
                }
            }
    }

    __syncthreads();
    if (tid < 128) {
        atomicMax(&g_hp[rowBase + tid], sHpR[tid]);
        atomicMin(&g_hn[rowBase + tid], sHnR[tid]);
        if (!diag) {
            atomicMax(&g_hp[colBase + tid], sHpC[tid]);
            atomicMin(&g_hn[colBase + tid], sHnC[tid]);
        }
    }
}

// ---------------------------------------------------------------------------
// Kernel 3: final masked-mean reduce. 1024 threads, vectorized int2 reads.
// ---------------------------------------------------------------------------
__global__ void loss_kernel(float* __restrict__ out) {
    __shared__ float ssum[1024];
    __shared__ float scnt[1024];
    const int tid = threadIdx.x;
    const int2* hp2 = reinterpret_cast<const int2*>(g_hp);
    const int2* hn2 = reinterpret_cast<const int2*>(g_hn);

    int2 hpa = hp2[tid],        hna = hn2[tid];
    int2 hpb = hp2[tid + 1024], hnb2 = hn2[tid + 1024];

    float sum = 0.f, cnt = 0.f;
    int hps[4] = {hpa.x, hpa.y, hpb.x, hpb.y};
    int hns[4] = {hna.x, hna.y, hnb2.x, hnb2.y};
#pragma unroll
    for (int k = 0; k < 4; k++) {
        bool valid = (hps[k] != (int)0xFF800000) && (hns[k] != 0x7F800000);
        if (valid) {
            float p = sqrtf(fmaxf(__int_as_float(hps[k]), LOSS_EPS));
            float n = sqrtf(fmaxf(__int_as_float(hns[k]), LOSS_EPS));
            sum += fmaxf(p - n + MARGIN, 0.f);
            cnt += 1.f;
        }
    }
    ssum[tid] = sum; scnt[tid] = cnt;
    __syncthreads();
    for (int s = 512; s; s >>= 1) {
        if (tid < s) { ssum[tid] += ssum[tid + s]; scnt[tid] += scnt[tid + s]; }
        __syncthreads();
    }
    if (tid == 0)
        out[0] = (scnt[0] > 0.f) ? (ssum[0] / fmaxf(scnt[0], 1.f)) : 0.f;
}

// ---------------------------------------------------------------------------
extern "C" void kernel_launch(void* const* d_in, const int* in_sizes, int n_in,
                              void* d_out, int out_size) {
    const float* emb    = (const float*)d_in[0];
    const int*   labels = (const int*)d_in[1];
    float*       out    = (float*)d_out;

    const int smemBytes = NSTAGE * STAGE_BYTES;   // 96 KB dynamic per CTA
    cudaFuncSetAttribute(mine_kernel, cudaFuncAttributeMaxDynamicSharedMemorySize,
                         smemBytes);

    prep_kernel<<<B / 4, 256>>>(emb);
    mine_kernel<<<NT * (NT + 1) / 2, 256, smemBytes>>>(labels);
    loss_kernel<<<1, 1024>>>(out);
}